// round 2
// baseline (speedup 1.0000x reference)
#include <cuda_runtime.h>
#include <cstdint>

#define B_    8
#define L_    4096
#define DM_   512
#define H_    8
#define D_    64
#define BH_   64
#define KTOP_ 8
#define M_    (B_ * L_)   // 32768

// ---------------- scratch (device globals; no allocations allowed) ----------
__device__ float  g_q[BH_ * L_ * D_];      // [bh][l][d]
__device__ float  g_k[BH_ * L_ * D_];
__device__ float  g_v[BH_ * L_ * D_];
__device__ float2 g_P[BH_ * D_ * L_];      // conj(Q)*K per (bh,d) over freq
__device__ float  g_corr[BH_ * L_];
__device__ float  g_w[BH_ * KTOP_];
__device__ int    g_i[BH_ * KTOP_];
__device__ float  g_ctx[B_ * L_ * DM_];

// ---------------- tf32 helpers ----------------------------------------------
__device__ __forceinline__ unsigned f2tf(float f) {
    unsigned u;
    asm("cvt.rna.tf32.f32 %0, %1;" : "=r"(u) : "f"(f));
    return u;
}

// ---------------- GEMM: C[m,n] = sum_k A[m,k]*W[n,k] + bias[n] ---------------
// 3xTF32 precision: a = hi + lo (both tf32); acc += ah*bh + ah*bl + al*bh.
// K = N = 512 fixed. MODE 0: row-major [M,512]. MODE 1: scatter to [B,H,L,D].
template <int MODE>
__global__ void __launch_bounds__(256) gemm512(const float* __restrict__ A,
                                               const float* __restrict__ W,
                                               const float* __restrict__ bias,
                                               float* __restrict__ out) {
    constexpr int K = 512;
    __shared__ __align__(16) float As[2][128][20];
    __shared__ __align__(16) float Ws[2][128][20];

    const int tid  = threadIdx.x;
    const int bm   = blockIdx.x * 128;
    const int bn   = blockIdx.y * 128;
    const int warp = tid >> 5, lane = tid & 31;
    const int g  = lane >> 2, tg = lane & 3;
    const int wm = (warp >> 1) * 32;  // 4 warps along M
    const int wn = (warp & 1) * 64;   // 2 warps along N

    float c[2][8][4];
#pragma unroll
    for (int i = 0; i < 2; i++)
#pragma unroll
        for (int j = 0; j < 8; j++)
#pragma unroll
            for (int r = 0; r < 4; r++) c[i][j][r] = 0.f;

    const int r0 = tid >> 2;          // 0..63
    const int c4 = (tid & 3) * 4;     // 0,4,8,12

    float4 a0, a1, w0, w1;
    auto load_tile = [&](int kt, float4& A0, float4& A1, float4& W0, float4& W1) {
        const int k0 = kt * 16;
        A0 = *(const float4*)&A[(size_t)(bm + r0) * K + k0 + c4];
        A1 = *(const float4*)&A[(size_t)(bm + r0 + 64) * K + k0 + c4];
        W0 = *(const float4*)&W[(size_t)(bn + r0) * K + k0 + c4];
        W1 = *(const float4*)&W[(size_t)(bn + r0 + 64) * K + k0 + c4];
    };
    auto store_tile = [&](int buf, float4 A0, float4 A1, float4 W0, float4 W1) {
        *(float4*)&As[buf][r0][c4]      = A0;
        *(float4*)&As[buf][r0 + 64][c4] = A1;
        *(float4*)&Ws[buf][r0][c4]      = W0;
        *(float4*)&Ws[buf][r0 + 64][c4] = W1;
    };
    auto compute = [&](int buf) {
#pragma unroll
        for (int kk = 0; kk < 2; kk++) {
            const int k0 = kk * 8;
            unsigned ah[2][4], al[2][4];
#pragma unroll
            for (int im = 0; im < 2; im++) {
                const int m0 = wm + im * 16;
                float f0 = As[buf][m0 + g][k0 + tg];
                float f1 = As[buf][m0 + g + 8][k0 + tg];
                float f2 = As[buf][m0 + g][k0 + tg + 4];
                float f3 = As[buf][m0 + g + 8][k0 + tg + 4];
                ah[im][0] = f2tf(f0); al[im][0] = f2tf(f0 - __uint_as_float(ah[im][0]));
                ah[im][1] = f2tf(f1); al[im][1] = f2tf(f1 - __uint_as_float(ah[im][1]));
                ah[im][2] = f2tf(f2); al[im][2] = f2tf(f2 - __uint_as_float(ah[im][2]));
                ah[im][3] = f2tf(f3); al[im][3] = f2tf(f3 - __uint_as_float(ah[im][3]));
            }
#pragma unroll
            for (int jn = 0; jn < 8; jn++) {
                const int n0 = wn + jn * 8;
                float bf0 = Ws[buf][n0 + g][k0 + tg];
                float bf1 = Ws[buf][n0 + g][k0 + tg + 4];
                unsigned bh0 = f2tf(bf0), bh1 = f2tf(bf1);
                unsigned bl0 = f2tf(bf0 - __uint_as_float(bh0));
                unsigned bl1 = f2tf(bf1 - __uint_as_float(bh1));
#pragma unroll
                for (int im = 0; im < 2; im++) {
                    asm volatile(
                        "mma.sync.aligned.m16n8k8.row.col.f32.tf32.tf32.f32 "
                        "{%0,%1,%2,%3},{%4,%5,%6,%7},{%8,%9},{%0,%1,%2,%3};"
                        : "+f"(c[im][jn][0]), "+f"(c[im][jn][1]),
                          "+f"(c[im][jn][2]), "+f"(c[im][jn][3])
                        : "r"(ah[im][0]), "r"(ah[im][1]), "r"(ah[im][2]),
                          "r"(ah[im][3]), "r"(bh0), "r"(bh1));
                    asm volatile(
                        "mma.sync.aligned.m16n8k8.row.col.f32.tf32.tf32.f32 "
                        "{%0,%1,%2,%3},{%4,%5,%6,%7},{%8,%9},{%0,%1,%2,%3};"
                        : "+f"(c[im][jn][0]), "+f"(c[im][jn][1]),
                          "+f"(c[im][jn][2]), "+f"(c[im][jn][3])
                        : "r"(ah[im][0]), "r"(ah[im][1]), "r"(ah[im][2]),
                          "r"(ah[im][3]), "r"(bl0), "r"(bl1));
                    asm volatile(
                        "mma.sync.aligned.m16n8k8.row.col.f32.tf32.tf32.f32 "
                        "{%0,%1,%2,%3},{%4,%5,%6,%7},{%8,%9},{%0,%1,%2,%3};"
                        : "+f"(c[im][jn][0]), "+f"(c[im][jn][1]),
                          "+f"(c[im][jn][2]), "+f"(c[im][jn][3])
                        : "r"(al[im][0]), "r"(al[im][1]), "r"(al[im][2]),
                          "r"(al[im][3]), "r"(bh0), "r"(bh1));
                }
            }
        }
    };

    load_tile(0, a0, a1, w0, w1);
    store_tile(0, a0, a1, w0, w1);
    __syncthreads();

    for (int kt = 0; kt < 32; kt++) {
        const int buf = kt & 1;
        float4 na0, na1, nw0, nw1;
        if (kt < 31) load_tile(kt + 1, na0, na1, nw0, nw1);
        compute(buf);
        if (kt < 31) store_tile(buf ^ 1, na0, na1, nw0, nw1);
        __syncthreads();
    }

    // epilogue
#pragma unroll
    for (int im = 0; im < 2; im++) {
#pragma unroll
        for (int jn = 0; jn < 8; jn++) {
            const int mrow = bm + wm + im * 16 + g;
            const int ncol = bn + wn + jn * 8 + 2 * tg;
            const float bv0 = bias[ncol], bv1 = bias[ncol + 1];
            float v00 = c[im][jn][0] + bv0;
            float v01 = c[im][jn][1] + bv1;
            float v10 = c[im][jn][2] + bv0;
            float v11 = c[im][jn][3] + bv1;
            if (MODE == 0) {
                out[(size_t)mrow * 512 + ncol]           = v00;
                out[(size_t)mrow * 512 + ncol + 1]       = v01;
                out[(size_t)(mrow + 8) * 512 + ncol]     = v10;
                out[(size_t)(mrow + 8) * 512 + ncol + 1] = v11;
            } else {
                const int h = ncol >> 6, d = ncol & 63;
                {
                    const int b = mrow >> 12, l = mrow & 4095;
                    size_t base = (((size_t)(b * 8 + h)) * 4096 + l) * 64 + d;
                    out[base]     = v00;
                    out[base + 1] = v01;
                }
                {
                    const int m2 = mrow + 8;
                    const int b = m2 >> 12, l = m2 & 4095;
                    size_t base = (((size_t)(b * 8 + h)) * 4096 + l) * 64 + d;
                    out[base]     = v10;
                    out[base + 1] = v11;
                }
            }
        }
    }
}

// ---------------- 4096-pt complex Stockham FFT in smem -----------------------
// x,y: ping-pong buffers of 4096 float2 each. Result ends in the buffer passed
// as x (12 stages = even number of swaps). 512 threads.
__device__ void fft4096(float2* x, float2* y, int tid) {
    int ls = 0;
#pragma unroll 1
    for (int stage = 0; stage < 12; stage++) {
        const int n = 4096 >> stage;
        const int m = n >> 1;
        const float inv_n = 1.0f / (float)n;
        const int s = 1 << ls;
#pragma unroll
        for (int t = tid; t < 2048; t += 512) {
            const int p = t >> ls;
            const int q = t & (s - 1);
            float sv, cv;
            sincospif(-2.0f * (float)p * inv_n, &sv, &cv);
            float2 a = x[q + s * p];
            float2 b = x[q + s * (p + m)];
            float2 e  = make_float2(a.x + b.x, a.y + b.y);
            float2 o  = make_float2(a.x - b.x, a.y - b.y);
            float2 ow = make_float2(o.x * cv - o.y * sv, o.x * sv + o.y * cv);
            y[q + s * (2 * p)]     = e;
            y[q + s * (2 * p + 1)] = ow;
        }
        __syncthreads();
        float2* tmp = x; x = y; y = tmp;
        ls++;
    }
}

// ---------------- Phase A: packed FFT(q+ik) -> conj(Q)*K ---------------------
__global__ void __launch_bounds__(512) fwd_corr_kernel() {
    extern __shared__ float2 sm[];
    float2* b0 = sm;
    float2* b1 = sm + 4096;
    const int bhd = blockIdx.x;
    const int bh = bhd >> 6, d = bhd & 63;
    const float* qp = g_q + (size_t)bh * L_ * D_ + d;
    const float* kp = g_k + (size_t)bh * L_ * D_ + d;
    for (int t = threadIdx.x; t < 4096; t += 512)
        b0[t] = make_float2(qp[(size_t)t * 64], kp[(size_t)t * 64]);
    __syncthreads();
    fft4096(b0, b1, threadIdx.x);

    float2* Pout = g_P + (size_t)bhd * L_;
    for (int f = threadIdx.x; f < 4096; f += 512) {
        float2 Z  = b0[f];
        float2 Zm = b0[(4096 - f) & 4095];
        // q real, k real packed as z = q + i*k
        float Qr = 0.5f * (Z.x + Zm.x);
        float Qi = 0.5f * (Z.y - Zm.y);
        float Kr = 0.5f * (Z.y + Zm.y);
        float Ki = 0.5f * (Zm.x - Z.x);
        // conj(Q)*K  (= conj(Q*conj(K)); lets phase B run a FORWARD fft)
        Pout[f] = make_float2(Qr * Kr + Qi * Ki, Qr * Ki - Qi * Kr);
    }
}

// ---------------- Phase B: sum over d, forward FFT, Re -> corr ---------------
__global__ void __launch_bounds__(512) inv_corr_kernel() {
    extern __shared__ float2 sm[];
    float2* b0 = sm;
    float2* b1 = sm + 4096;
    const int bh = blockIdx.x;
    float2 acc[8];
#pragma unroll
    for (int j = 0; j < 8; j++) acc[j] = make_float2(0.f, 0.f);
    const float2* Pp = g_P + (size_t)bh * 64 * L_;
    for (int d = 0; d < 64; d++) {
#pragma unroll
        for (int j = 0; j < 8; j++) {
            float2 v = Pp[(size_t)d * L_ + threadIdx.x + j * 512];
            acc[j].x += v.x;
            acc[j].y += v.y;
        }
    }
#pragma unroll
    for (int j = 0; j < 8; j++) b0[threadIdx.x + j * 512] = acc[j];
    __syncthreads();
    fft4096(b0, b1, threadIdx.x);
    const float sc = 1.0f / (4096.0f * 64.0f);   // irfft 1/L and mean 1/D
    for (int t = threadIdx.x; t < 4096; t += 512)
        g_corr[(size_t)bh * L_ + t] = b0[t].x * sc;
}

// ---------------- Phase C: top-8 + softmax -----------------------------------
__global__ void __launch_bounds__(256) topk_kernel() {
    const int bh = blockIdx.x;
    const float* cr = g_corr + (size_t)bh * L_;
    __shared__ float svals[256];
    __shared__ int   sidx[256];
    __shared__ int   chosen[KTOP_];
    __shared__ float chval[KTOP_];
    const int tid = threadIdx.x;
    for (int it = 0; it < KTOP_; it++) {
        float best = -3.0e38f;
        int bi = -1;
        for (int t = tid; t < 4096; t += 256) {
            float v = cr[t];
            bool used = false;
            for (int u = 0; u < it; u++)
                if (chosen[u] == t) used = true;
            if (!used && (v > best || (v == best && t < bi))) { best = v; bi = t; }
        }
        svals[tid] = best;
        sidx[tid] = bi;
        __syncthreads();
        for (int off = 128; off > 0; off >>= 1) {
            if (tid < off) {
                if (svals[tid + off] > svals[tid] ||
                    (svals[tid + off] == svals[tid] && sidx[tid + off] < sidx[tid])) {
                    svals[tid] = svals[tid + off];
                    sidx[tid]  = sidx[tid + off];
                }
            }
            __syncthreads();
        }
        if (tid == 0) { chosen[it] = sidx[0]; chval[it] = svals[0]; }
        __syncthreads();
    }
    if (tid == 0) {
        float mx = chval[0];  // iteration 0 found the global max
        float e[KTOP_], se = 0.f;
        for (int u = 0; u < KTOP_; u++) { e[u] = expf(chval[u] - mx); se += e[u]; }
        float inv = 1.0f / se;
        for (int u = 0; u < KTOP_; u++) {
            g_w[bh * KTOP_ + u] = e[u] * inv;
            g_i[bh * KTOP_ + u] = chosen[u];
        }
    }
}

// ---------------- Phase D: weighted circular gather of V ---------------------
__global__ void __launch_bounds__(256) gather_kernel() {
    const int bh = blockIdx.y;
    const int b = bh >> 3, h = bh & 7;
    const int li = threadIdx.x >> 6;
    const int d  = threadIdx.x & 63;
    const int l  = blockIdx.x * 4 + li;
    __shared__ float w[KTOP_];
    __shared__ int   ix[KTOP_];
    if (threadIdx.x < KTOP_) {
        w[threadIdx.x]  = g_w[bh * KTOP_ + threadIdx.x];
        ix[threadIdx.x] = g_i[bh * KTOP_ + threadIdx.x];
    }
    __syncthreads();
    const float* vp = g_v + (size_t)bh * L_ * D_;
    float acc = 0.f;
#pragma unroll
    for (int u = 0; u < KTOP_; u++) {
        const int src = (l + ix[u]) & 4095;
        acc += w[u] * vp[(size_t)src * 64 + d];
    }
    g_ctx[((size_t)(b * L_ + l)) * DM_ + h * 64 + d] = acc;
}

// ---------------- launch ------------------------------------------------------
extern "C" void kernel_launch(void* const* d_in, const int* in_sizes, int n_in,
                              void* d_out, int out_size) {
    const float* x  = (const float*)d_in[0];
    const float* Wq = (const float*)d_in[1];
    const float* bq = (const float*)d_in[2];
    const float* Wk = (const float*)d_in[3];
    const float* bk = (const float*)d_in[4];
    const float* Wv = (const float*)d_in[5];
    const float* bv = (const float*)d_in[6];
    const float* Wo = (const float*)d_in[7];
    const float* bo = (const float*)d_in[8];
    float* out = (float*)d_out;

    float *qp, *kp, *vp, *ctxp;
    cudaGetSymbolAddress((void**)&qp, g_q);
    cudaGetSymbolAddress((void**)&kp, g_k);
    cudaGetSymbolAddress((void**)&vp, g_v);
    cudaGetSymbolAddress((void**)&ctxp, g_ctx);

    cudaFuncSetAttribute(fwd_corr_kernel,
                         cudaFuncAttributeMaxDynamicSharedMemorySize, 65536);
    cudaFuncSetAttribute(inv_corr_kernel,
                         cudaFuncAttributeMaxDynamicSharedMemorySize, 65536);

    dim3 gg(M_ / 128, 4);
    gemm512<1><<<gg, 256>>>(x, Wq, bq, qp);
    gemm512<1><<<gg, 256>>>(x, Wk, bk, kp);
    gemm512<1><<<gg, 256>>>(x, Wv, bv, vp);
    fwd_corr_kernel<<<4096, 512, 65536>>>();
    inv_corr_kernel<<<64, 512, 65536>>>();
    topk_kernel<<<64, 256>>>();
    gather_kernel<<<dim3(1024, 64), 256>>>();
    gemm512<0><<<gg, 256>>>(ctxp, Wo, bo, out);
}

// round 3
// speedup vs baseline: 1.1891x; 1.1891x over previous
#include <cuda_runtime.h>
#include <cstdint>

#define B_    8
#define L_    4096
#define DM_   512
#define H_    8
#define D_    64
#define BH_   64
#define KTOP_ 8
#define M_    (B_ * L_)   // 32768

// ---------------- scratch (device globals; no allocations allowed) ----------
__device__ float  g_q[BH_ * D_ * L_];      // [bh][d][l]  (transposed!)
__device__ float  g_k[BH_ * D_ * L_];      // [bh][d][l]
__device__ float  g_v[BH_ * L_ * D_];      // [bh][l][d]
__device__ float2 g_P[BH_ * 8 * L_];       // per-(bh,group-of-8-d) partial sums
__device__ float  g_corr[BH_ * L_];
__device__ float  g_w[BH_ * KTOP_];
__device__ int    g_i[BH_ * KTOP_];
__device__ float  g_ctx[B_ * L_ * DM_];

// ---------------- tf32 helpers ----------------------------------------------
__device__ __forceinline__ unsigned f2tf(float f) {
    unsigned u;
    asm("cvt.rna.tf32.f32 %0, %1;" : "=r"(u) : "f"(f));
    return u;
}

__device__ __forceinline__ void cp16(void* smem, const void* gmem) {
    unsigned s = (unsigned)__cvta_generic_to_shared(smem);
    asm volatile("cp.async.cg.shared.global [%0], [%1], 16;" :: "r"(s), "l"(gmem));
}

// ---------------- GEMM: C[m,n] = sum_k A[m,k]*W[n,k] + bias[n] ---------------
// 3xTF32 precision: a = hi + lo (both tf32); acc += ah*bh + ah*bl + al*bh.
// K = N = 512. MODE 0: row-major [M,512]. MODE 1: scatter to [B,H,L,D].
// MODE 2: scatter transposed to [B,H,D,L].
template <int MODE>
__global__ void __launch_bounds__(256) gemm512(const float* __restrict__ A,
                                               const float* __restrict__ W,
                                               const float* __restrict__ bias,
                                               float* __restrict__ out) {
    constexpr int K = 512;
    __shared__ __align__(16) float As[2][128][20];
    __shared__ __align__(16) float Ws[2][128][20];

    const int tid  = threadIdx.x;
    const int bm   = blockIdx.x * 128;
    const int bn   = blockIdx.y * 128;
    const int warp = tid >> 5, lane = tid & 31;
    const int g  = lane >> 2, tg = lane & 3;
    const int wm = (warp >> 1) * 32;  // 4 warps along M
    const int wn = (warp & 1) * 64;   // 2 warps along N

    float c[2][8][4];
#pragma unroll
    for (int i = 0; i < 2; i++)
#pragma unroll
        for (int j = 0; j < 8; j++)
#pragma unroll
            for (int r = 0; r < 4; r++) c[i][j][r] = 0.f;

    const int r0 = tid >> 2;          // 0..63
    const int c4 = (tid & 3) * 4;     // 0,4,8,12

    auto cp_tile = [&](int buf, int kt) {
        const int k0 = kt * 16;
        cp16(&As[buf][r0][c4],      &A[(size_t)(bm + r0) * K + k0 + c4]);
        cp16(&As[buf][r0 + 64][c4], &A[(size_t)(bm + r0 + 64) * K + k0 + c4]);
        cp16(&Ws[buf][r0][c4],      &W[(size_t)(bn + r0) * K + k0 + c4]);
        cp16(&Ws[buf][r0 + 64][c4], &W[(size_t)(bn + r0 + 64) * K + k0 + c4]);
        asm volatile("cp.async.commit_group;" ::: "memory");
    };

    auto compute = [&](int buf) {
#pragma unroll
        for (int kk = 0; kk < 2; kk++) {
            const int k0 = kk * 8;
            unsigned ah[2][4], al[2][4];
#pragma unroll
            for (int im = 0; im < 2; im++) {
                const int m0 = wm + im * 16;
                float f0 = As[buf][m0 + g][k0 + tg];
                float f1 = As[buf][m0 + g + 8][k0 + tg];
                float f2 = As[buf][m0 + g][k0 + tg + 4];
                float f3 = As[buf][m0 + g + 8][k0 + tg + 4];
                ah[im][0] = f2tf(f0); al[im][0] = f2tf(f0 - __uint_as_float(ah[im][0]));
                ah[im][1] = f2tf(f1); al[im][1] = f2tf(f1 - __uint_as_float(ah[im][1]));
                ah[im][2] = f2tf(f2); al[im][2] = f2tf(f2 - __uint_as_float(ah[im][2]));
                ah[im][3] = f2tf(f3); al[im][3] = f2tf(f3 - __uint_as_float(ah[im][3]));
            }
#pragma unroll
            for (int jn = 0; jn < 8; jn++) {
                const int n0 = wn + jn * 8;
                float bf0 = Ws[buf][n0 + g][k0 + tg];
                float bf1 = Ws[buf][n0 + g][k0 + tg + 4];
                unsigned bh0 = f2tf(bf0), bh1 = f2tf(bf1);
                unsigned bl0 = f2tf(bf0 - __uint_as_float(bh0));
                unsigned bl1 = f2tf(bf1 - __uint_as_float(bh1));
#pragma unroll
                for (int im = 0; im < 2; im++) {
                    asm volatile(
                        "mma.sync.aligned.m16n8k8.row.col.f32.tf32.tf32.f32 "
                        "{%0,%1,%2,%3},{%4,%5,%6,%7},{%8,%9},{%0,%1,%2,%3};"
                        : "+f"(c[im][jn][0]), "+f"(c[im][jn][1]),
                          "+f"(c[im][jn][2]), "+f"(c[im][jn][3])
                        : "r"(ah[im][0]), "r"(ah[im][1]), "r"(ah[im][2]),
                          "r"(ah[im][3]), "r"(bh0), "r"(bh1));
                    asm volatile(
                        "mma.sync.aligned.m16n8k8.row.col.f32.tf32.tf32.f32 "
                        "{%0,%1,%2,%3},{%4,%5,%6,%7},{%8,%9},{%0,%1,%2,%3};"
                        : "+f"(c[im][jn][0]), "+f"(c[im][jn][1]),
                          "+f"(c[im][jn][2]), "+f"(c[im][jn][3])
                        : "r"(ah[im][0]), "r"(ah[im][1]), "r"(ah[im][2]),
                          "r"(ah[im][3]), "r"(bl0), "r"(bl1));
                    asm volatile(
                        "mma.sync.aligned.m16n8k8.row.col.f32.tf32.tf32.f32 "
                        "{%0,%1,%2,%3},{%4,%5,%6,%7},{%8,%9},{%0,%1,%2,%3};"
                        : "+f"(c[im][jn][0]), "+f"(c[im][jn][1]),
                          "+f"(c[im][jn][2]), "+f"(c[im][jn][3])
                        : "r"(al[im][0]), "r"(al[im][1]), "r"(al[im][2]),
                          "r"(al[im][3]), "r"(bh0), "r"(bh1));
                }
            }
        }
    };

    cp_tile(0, 0);
    for (int kt = 0; kt < 32; kt++) {
        const int buf = kt & 1;
        asm volatile("cp.async.wait_group 0;" ::: "memory");
        __syncthreads();
        if (kt < 31) cp_tile(buf ^ 1, kt + 1);
        compute(buf);
    }

    // epilogue
#pragma unroll
    for (int im = 0; im < 2; im++) {
#pragma unroll
        for (int jn = 0; jn < 8; jn++) {
            const int mrow = bm + wm + im * 16 + g;
            const int ncol = bn + wn + jn * 8 + 2 * tg;
            const float bv0 = bias[ncol], bv1 = bias[ncol + 1];
            float v00 = c[im][jn][0] + bv0;
            float v01 = c[im][jn][1] + bv1;
            float v10 = c[im][jn][2] + bv0;
            float v11 = c[im][jn][3] + bv1;
            if (MODE == 0) {
                out[(size_t)mrow * 512 + ncol]           = v00;
                out[(size_t)mrow * 512 + ncol + 1]       = v01;
                out[(size_t)(mrow + 8) * 512 + ncol]     = v10;
                out[(size_t)(mrow + 8) * 512 + ncol + 1] = v11;
            } else if (MODE == 1) {
                const int h = ncol >> 6, d = ncol & 63;
                const int b = mrow >> 12, l = mrow & 4095;
                size_t base = (((size_t)(b * 8 + h)) * 4096 + l) * 64 + d;
                out[base]     = v00;
                out[base + 1] = v01;
                out[base + 8 * 64]     = v10;     // l+8 in same (b,h)
                out[base + 8 * 64 + 1] = v11;
            } else {
                // MODE 2: [bh][d][l];  (b*8+h)*64+d == b*512 + ncol
                const int b = mrow >> 12, l = mrow & 4095;
                size_t base = ((size_t)(b * 512 + ncol)) * 4096 + l;
                out[base]        = v00;
                out[base + 4096] = v01;           // d+1
                out[base + 8]        = v10;       // l+8
                out[base + 4096 + 8] = v11;
            }
        }
    }
}

// ---------------- 4096-pt complex Stockham FFT in smem (table twiddles) ------
// x,y: ping-pong buffers of 4096 float2. Result ends in buffer passed as x.
// tw[j] = exp(-2*pi*i*j/4096), j in [0,2048). 512 threads.
__device__ void fft4096t(float2* x, float2* y, const float2* tw, int tid) {
    int ls = 0;
#pragma unroll 1
    for (int stage = 0; stage < 12; stage++) {
        const int n = 4096 >> stage;
        const int m = n >> 1;
        const int s = 1 << ls;
#pragma unroll
        for (int t = tid; t < 2048; t += 512) {
            const int p = t >> ls;
            const int q = t & (s - 1);
            float2 w = tw[p << ls];
            float2 a = x[q + s * p];
            float2 b = x[q + s * (p + m)];
            float2 e  = make_float2(a.x + b.x, a.y + b.y);
            float2 o  = make_float2(a.x - b.x, a.y - b.y);
            float2 ow = make_float2(o.x * w.x - o.y * w.y, o.x * w.y + o.y * w.x);
            y[q + s * (2 * p)]     = e;
            y[q + s * (2 * p + 1)] = ow;
        }
        __syncthreads();
        float2* tmp = x; x = y; y = tmp;
        ls++;
    }
}

// ---------------- Phase A: packed FFT(q+ik), 8 d's per block, reduce ---------
__global__ void __launch_bounds__(512) fwd_corr_kernel() {
    extern __shared__ float2 sm[];
    float2* b0 = sm;            // 4096
    float2* b1 = sm + 4096;     // 4096
    float2* tw = sm + 8192;     // 2048
    const int tid = threadIdx.x;
    for (int j = tid; j < 2048; j += 512) {
        float s, c;
        sincospif(-(float)j / 2048.0f, &s, &c);
        tw[j] = make_float2(c, s);
    }
    const int bh = blockIdx.x >> 3, grp = blockIdx.x & 7;
    const float* qb = g_q + ((size_t)bh * 64 + grp * 8) * 4096;
    const float* kb = g_k + ((size_t)bh * 64 + grp * 8) * 4096;

    float2 acc[8];
#pragma unroll
    for (int j = 0; j < 8; j++) acc[j] = make_float2(0.f, 0.f);

    for (int dd = 0; dd < 8; dd++) {
        const float* qp = qb + (size_t)dd * 4096;
        const float* kp = kb + (size_t)dd * 4096;
        __syncthreads();   // previous iteration's reads of b0 complete
#pragma unroll
        for (int j = 0; j < 8; j++) {
            int t = tid + j * 512;
            b0[t] = make_float2(qp[t], kp[t]);
        }
        __syncthreads();
        fft4096t(b0, b1, tw, tid);
#pragma unroll
        for (int j = 0; j < 8; j++) {
            int f = tid + j * 512;
            float2 Z  = b0[f];
            float2 Zm = b0[(4096 - f) & 4095];
            float Qr = 0.5f * (Z.x + Zm.x);
            float Qi = 0.5f * (Z.y - Zm.y);
            float Kr = 0.5f * (Z.y + Zm.y);
            float Ki = 0.5f * (Zm.x - Z.x);
            acc[j].x += Qr * Kr + Qi * Ki;   // conj(Q)*K
            acc[j].y += Qr * Ki - Qi * Kr;
        }
    }
    float2* Pout = g_P + (size_t)blockIdx.x * 4096;
#pragma unroll
    for (int j = 0; j < 8; j++) Pout[tid + j * 512] = acc[j];
}

// ---------------- Phase B: sum 8 partials, forward FFT, Re -> corr -----------
__global__ void __launch_bounds__(512) inv_corr_kernel() {
    extern __shared__ float2 sm[];
    float2* b0 = sm;
    float2* b1 = sm + 4096;
    float2* tw = sm + 8192;
    const int tid = threadIdx.x;
    for (int j = tid; j < 2048; j += 512) {
        float s, c;
        sincospif(-(float)j / 2048.0f, &s, &c);
        tw[j] = make_float2(c, s);
    }
    const int bh = blockIdx.x;
    const float2* Pp = g_P + (size_t)bh * 8 * 4096;
    float2 acc[8];
#pragma unroll
    for (int j = 0; j < 8; j++) acc[j] = make_float2(0.f, 0.f);
    for (int grp = 0; grp < 8; grp++) {
#pragma unroll
        for (int j = 0; j < 8; j++) {
            float2 v = Pp[(size_t)grp * 4096 + tid + j * 512];
            acc[j].x += v.x;
            acc[j].y += v.y;
        }
    }
#pragma unroll
    for (int j = 0; j < 8; j++) b0[tid + j * 512] = acc[j];
    __syncthreads();
    fft4096t(b0, b1, tw, tid);
    const float sc = 1.0f / (4096.0f * 64.0f);   // irfft 1/L and mean 1/D
    for (int t = tid; t < 4096; t += 512)
        g_corr[(size_t)bh * L_ + t] = b0[t].x * sc;
}

// ---------------- Phase C: top-8 + softmax (corr cached in smem) -------------
__global__ void __launch_bounds__(256) topk_kernel() {
    const int bh = blockIdx.x;
    const float* cr = g_corr + (size_t)bh * L_;
    __shared__ float scr[4096];
    __shared__ float svals[256];
    __shared__ int   sidx[256];
    __shared__ int   chosen[KTOP_];
    __shared__ float chval[KTOP_];
    const int tid = threadIdx.x;
    for (int t = tid; t < 4096; t += 256) scr[t] = cr[t];
    __syncthreads();
    for (int it = 0; it < KTOP_; it++) {
        float best = -3.0e38f;
        int bi = -1;
        for (int t = tid; t < 4096; t += 256) {
            float v = scr[t];
            bool used = false;
            for (int u = 0; u < it; u++)
                if (chosen[u] == t) used = true;
            if (!used && (v > best || (v == best && t < bi))) { best = v; bi = t; }
        }
        svals[tid] = best;
        sidx[tid] = bi;
        __syncthreads();
        for (int off = 128; off > 0; off >>= 1) {
            if (tid < off) {
                if (svals[tid + off] > svals[tid] ||
                    (svals[tid + off] == svals[tid] && sidx[tid + off] < sidx[tid])) {
                    svals[tid] = svals[tid + off];
                    sidx[tid]  = sidx[tid + off];
                }
            }
            __syncthreads();
        }
        if (tid == 0) { chosen[it] = sidx[0]; chval[it] = svals[0]; }
        __syncthreads();
    }
    if (tid == 0) {
        float mx = chval[0];  // iteration 0 found the global max
        float e[KTOP_], se = 0.f;
        for (int u = 0; u < KTOP_; u++) { e[u] = expf(chval[u] - mx); se += e[u]; }
        float inv = 1.0f / se;
        for (int u = 0; u < KTOP_; u++) {
            g_w[bh * KTOP_ + u] = e[u] * inv;
            g_i[bh * KTOP_ + u] = chosen[u];
        }
    }
}

// ---------------- Phase D: weighted circular gather of V ---------------------
__global__ void __launch_bounds__(256) gather_kernel() {
    const int bh = blockIdx.y;
    const int b = bh >> 3, h = bh & 7;
    const int li = threadIdx.x >> 6;
    const int d  = threadIdx.x & 63;
    const int l  = blockIdx.x * 4 + li;
    __shared__ float w[KTOP_];
    __shared__ int   ix[KTOP_];
    if (threadIdx.x < KTOP_) {
        w[threadIdx.x]  = g_w[bh * KTOP_ + threadIdx.x];
        ix[threadIdx.x] = g_i[bh * KTOP_ + threadIdx.x];
    }
    __syncthreads();
    const float* vp = g_v + (size_t)bh * L_ * D_;
    float acc = 0.f;
#pragma unroll
    for (int u = 0; u < KTOP_; u++) {
        const int src = (l + ix[u]) & 4095;
        acc += w[u] * vp[(size_t)src * 64 + d];
    }
    g_ctx[((size_t)(b * L_ + l)) * DM_ + h * 64 + d] = acc;
}

// ---------------- launch ------------------------------------------------------
extern "C" void kernel_launch(void* const* d_in, const int* in_sizes, int n_in,
                              void* d_out, int out_size) {
    const float* x  = (const float*)d_in[0];
    const float* Wq = (const float*)d_in[1];
    const float* bq = (const float*)d_in[2];
    const float* Wk = (const float*)d_in[3];
    const float* bk = (const float*)d_in[4];
    const float* Wv = (const float*)d_in[5];
    const float* bv = (const float*)d_in[6];
    const float* Wo = (const float*)d_in[7];
    const float* bo = (const float*)d_in[8];
    float* out = (float*)d_out;

    float *qp, *kp, *vp, *ctxp;
    cudaGetSymbolAddress((void**)&qp, g_q);
    cudaGetSymbolAddress((void**)&kp, g_k);
    cudaGetSymbolAddress((void**)&vp, g_v);
    cudaGetSymbolAddress((void**)&ctxp, g_ctx);

    cudaFuncSetAttribute(fwd_corr_kernel,
                         cudaFuncAttributeMaxDynamicSharedMemorySize, 81920);
    cudaFuncSetAttribute(inv_corr_kernel,
                         cudaFuncAttributeMaxDynamicSharedMemorySize, 81920);

    dim3 gg(M_ / 128, 4);
    gemm512<2><<<gg, 256>>>(x, Wq, bq, qp);
    gemm512<2><<<gg, 256>>>(x, Wk, bk, kp);
    gemm512<1><<<gg, 256>>>(x, Wv, bv, vp);
    fwd_corr_kernel<<<512, 512, 81920>>>();
    inv_corr_kernel<<<64, 512, 81920>>>();
    topk_kernel<<<64, 256>>>();
    gather_kernel<<<dim3(1024, 64), 256>>>();
    gemm512<0><<<gg, 256>>>(ctxp, Wo, bo, out);
}